// round 1
// baseline (speedup 1.0000x reference)
#include <cuda_runtime.h>
#include <math.h>

#define NB 32768
#define DIN 784
#define DH 1024
#define DLAT 64
#define NK 8192

typedef unsigned long long u64;

// Scratch (device globals are the allowed scratch mechanism)
__device__ float g_h1[(size_t)NB * DH];     // 128 MB
__device__ float g_h2[(size_t)NB * DH];     // 128 MB
__device__ float g_enorm[NK];
__device__ int   g_idx[NB];

__device__ __forceinline__ u64 pack2(float lo, float hi) {
    u64 r; asm("mov.b64 %0, {%1,%2};" : "=l"(r) : "f"(lo), "f"(hi)); return r;
}
__device__ __forceinline__ void unpack2(u64 v, float& lo, float& hi) {
    asm("mov.b64 {%0,%1}, %2;" : "=f"(lo), "=f"(hi) : "l"(v));
}
__device__ __forceinline__ void fma2(u64& acc, u64 a, u64 b) {
    asm("fma.rn.f32x2 %0, %1, %2, %0;" : "+l"(acc) : "l"(a), "l"(b));
}

// ---------------------------------------------------------------------------
// Generic SGEMM: C[M,N] = act(A[M,Kd] @ W[Kd,N] + bias[N])
// BMxBN tile, 8x8 per thread, f32x2 packed micro-kernel.
// Requirements: M % BM == 0, Kd % BK == 0, N % 4 == 0 (N may be < grid cover).
// ACT: 0 = none, 1 = relu, 2 = sigmoid
// ---------------------------------------------------------------------------
template<int BM, int BN, int BK, int ACT>
__global__ void __launch_bounds__((BM/8)*(BN/8))
sgemm_bias_act(const float* __restrict__ A, const float* __restrict__ W,
               const float* __restrict__ bias, float* __restrict__ C,
               int M, int N, int Kd)
{
    constexpr int TM = 8, TN = 8;
    constexpr int THREADS = (BM/TM) * (BN/TN);

    __shared__ __align__(16) float As[BK][BM];
    __shared__ __align__(16) float Ws[BK][BN];

    const int tid = threadIdx.x;
    const int tx  = tid % (BN/TN);
    const int ty  = tid / (BN/TN);
    const int m0  = blockIdx.y * BM;
    const int n0  = blockIdx.x * BN;

    u64 acc[TM][TN/2];
    #pragma unroll
    for (int i = 0; i < TM; i++)
        #pragma unroll
        for (int j = 0; j < TN/2; j++) acc[i][j] = 0ull;

    for (int k0 = 0; k0 < Kd; k0 += BK) {
        // Load A tile (BM x BK), store transposed As[k][m]
        constexpr int AV = (BM * BK) / (THREADS * 4);
        #pragma unroll
        for (int it = 0; it < AV; ++it) {
            int li = tid + it * THREADS;       // [0, BM*BK/4)
            int m  = li / (BK/4);
            int kq = li % (BK/4);
            float4 v = *reinterpret_cast<const float4*>(
                &A[(size_t)(m0 + m) * Kd + k0 + kq*4]);
            As[kq*4+0][m] = v.x; As[kq*4+1][m] = v.y;
            As[kq*4+2][m] = v.z; As[kq*4+3][m] = v.w;
        }
        // Load W tile (BK x BN), natural layout, N-guarded
        constexpr int WV = (BK * BN) / (THREADS * 4);
        #pragma unroll
        for (int it = 0; it < WV; ++it) {
            int li = tid + it * THREADS;       // [0, BK*BN/4)
            int k  = li / (BN/4);
            int nq = li % (BN/4);
            int n  = n0 + nq*4;
            float4 v = make_float4(0.f, 0.f, 0.f, 0.f);
            if (n < N)
                v = *reinterpret_cast<const float4*>(&W[(size_t)(k0 + k) * N + n]);
            *reinterpret_cast<float4*>(&Ws[k][nq*4]) = v;
        }
        __syncthreads();

        #pragma unroll
        for (int k = 0; k < BK; k++) {
            float4 av0 = *reinterpret_cast<const float4*>(&As[k][ty*TM]);
            float4 av1 = *reinterpret_cast<const float4*>(&As[k][ty*TM + 4]);
            float a[TM] = {av0.x, av0.y, av0.z, av0.w, av1.x, av1.y, av1.z, av1.w};
            const u64* wrow = reinterpret_cast<const u64*>(&Ws[k][tx*TN]);
            u64 b2[TN/2];
            #pragma unroll
            for (int j = 0; j < TN/2; j++) b2[j] = wrow[j];
            #pragma unroll
            for (int i = 0; i < TM; i++) {
                u64 ad = pack2(a[i], a[i]);
                #pragma unroll
                for (int j = 0; j < TN/2; j++) fma2(acc[i][j], ad, b2[j]);
            }
        }
        __syncthreads();
    }

    // Epilogue
    #pragma unroll
    for (int i = 0; i < TM; i++) {
        int m = m0 + ty*TM + i;
        #pragma unroll
        for (int j = 0; j < TN/2; j++) {
            int n = n0 + tx*TN + j*2;
            if (n < N) {
                float lo, hi; unpack2(acc[i][j], lo, hi);
                lo += bias[n]; hi += bias[n+1];
                if (ACT == 1) { lo = fmaxf(lo, 0.f); hi = fmaxf(hi, 0.f); }
                else if (ACT == 2) {
                    lo = 1.0f / (1.0f + expf(-lo));
                    hi = 1.0f / (1.0f + expf(-hi));
                }
                *reinterpret_cast<float2*>(&C[(size_t)m * N + n]) = make_float2(lo, hi);
            }
        }
    }
}

// ---------------------------------------------------------------------------
// emb row norms: one warp per code, 64 dims
// ---------------------------------------------------------------------------
__global__ void emb_norms_kernel(const float* __restrict__ emb,
                                 float* __restrict__ enorm)
{
    int gwarp = (blockIdx.x * blockDim.x + threadIdx.x) >> 5;
    int lane  = threadIdx.x & 31;
    if (gwarp >= NK) return;
    float a = emb[(size_t)gwarp * 64 + lane];
    float b = emb[(size_t)gwarp * 64 + 32 + lane];
    float s = a*a + b*b;
    #pragma unroll
    for (int off = 16; off; off >>= 1) s += __shfl_xor_sync(0xffffffffu, s, off);
    if (lane == 0) enorm[gwarp] = s;
}

// ---------------------------------------------------------------------------
// Fused distance GEMM + argmin.
// Block = 128 rows of z_e. Loop over K in chunks of 64 codes.
// Smem holds pre-packed f32x2 pairs in [j2][row] transposed layout:
//   conflict-free LDS.64 in the inner loop by construction.
// Thread (tx=tid&7, ty=tid>>3): 4 rows (ty*4+i), 8 codes (j*8+tx per chunk).
// Ranking key: ||e||^2 - 2 z.e  (row-constant ||z||^2 dropped; same argmin).
// Tie-break = first occurrence (strict <, ascending code order everywhere).
// ---------------------------------------------------------------------------
__global__ void __launch_bounds__(256)
argmin_kernel(const float* __restrict__ ze, const float* __restrict__ emb,
              const float* __restrict__ enorm, int* __restrict__ out_idx)
{
    __shared__ __align__(16) u64 Zs2[32 * 128];  // [j2][row]   32 KB
    __shared__ __align__(16) u64 Es2[32 * 64];   // [j2][code]  16 KB

    const int tid = threadIdx.x;
    const int tx  = tid & 7;
    const int ty  = tid >> 3;
    const int m0  = blockIdx.x * 128;

    // Load z_e tile, pre-packed + transposed
    #pragma unroll
    for (int it = 0; it < 8; ++it) {
        int li  = tid + it * 256;     // [0, 2048)
        int row = li & 127;
        int q   = li >> 7;            // float4 index 0..15
        float4 v = *reinterpret_cast<const float4*>(
            &ze[(size_t)(m0 + row) * 64 + q*4]);
        Zs2[(q*2+0) * 128 + row] = pack2(v.x, v.y);
        Zs2[(q*2+1) * 128 + row] = pack2(v.z, v.w);
    }

    float bestv[4]; int besti[4];
    #pragma unroll
    for (int i = 0; i < 4; i++) { bestv[i] = 3.4e38f; besti[i] = 0; }

    for (int c = 0; c < NK/64; ++c) {
        __syncthreads();
        #pragma unroll
        for (int it = 0; it < 4; ++it) {
            int li   = tid + it * 256;   // [0, 1024)
            int code = li & 63;
            int q    = li >> 6;          // 0..15
            float4 v = *reinterpret_cast<const float4*>(
                &emb[(size_t)(c*64 + code) * 64 + q*4]);
            Es2[(q*2+0) * 64 + code] = pack2(v.x, v.y);
            Es2[(q*2+1) * 64 + code] = pack2(v.z, v.w);
        }
        __syncthreads();

        // prefetch norms for this thread's 8 codes
        float en[8];
        #pragma unroll
        for (int j = 0; j < 8; j++) en[j] = enorm[c*64 + j*8 + tx];

        u64 acc[4][8];
        #pragma unroll
        for (int i = 0; i < 4; i++)
            #pragma unroll
            for (int j = 0; j < 8; j++) acc[i][j] = 0ull;

        #pragma unroll 4
        for (int j2 = 0; j2 < 32; ++j2) {
            u64 zp[4], ep[8];
            #pragma unroll
            for (int i = 0; i < 4; i++) zp[i] = Zs2[j2*128 + ty*4 + i];
            #pragma unroll
            for (int j = 0; j < 8; j++) ep[j] = Es2[j2*64 + j*8 + tx];
            #pragma unroll
            for (int i = 0; i < 4; i++)
                #pragma unroll
                for (int j = 0; j < 8; j++) fma2(acc[i][j], zp[i], ep[j]);
        }

        #pragma unroll
        for (int i = 0; i < 4; i++) {
            #pragma unroll
            for (int j = 0; j < 8; j++) {
                float lo, hi; unpack2(acc[i][j], lo, hi);
                float r = en[j] - 2.0f * (lo + hi);
                int code = c*64 + j*8 + tx;
                if (r < bestv[i]) { bestv[i] = r; besti[i] = code; }
            }
        }
    }

    // Reduce over the 8 lanes sharing a row (same warp, lane group of 8)
    #pragma unroll
    for (int i = 0; i < 4; i++) {
        float v = bestv[i]; int ii = besti[i];
        #pragma unroll
        for (int off = 4; off; off >>= 1) {
            float ov = __shfl_xor_sync(0xffffffffu, v,  off, 8);
            int   oi = __shfl_xor_sync(0xffffffffu, ii, off, 8);
            if (ov < v || (ov == v && oi < ii)) { v = ov; ii = oi; }
        }
        if (tx == 0) out_idx[m0 + ty*4 + i] = ii;
    }
}

// ---------------------------------------------------------------------------
// z_q gather
// ---------------------------------------------------------------------------
__global__ void gather_zq_kernel(const int* __restrict__ idx,
                                 const float* __restrict__ emb,
                                 float* __restrict__ zq)
{
    int t = blockIdx.x * blockDim.x + threadIdx.x;   // [0, NB*64)
    int b = t >> 6, j = t & 63;
    zq[t] = emb[(size_t)idx[b] * 64 + j];
}

// ---------------------------------------------------------------------------
extern "C" void kernel_launch(void* const* d_in, const int* in_sizes, int n_in,
                              void* d_out, int out_size)
{
    const float* x   = (const float*)d_in[0];
    const float* W1  = (const float*)d_in[1];
    const float* b1  = (const float*)d_in[2];
    const float* W2  = (const float*)d_in[3];
    const float* b2  = (const float*)d_in[4];
    const float* W3  = (const float*)d_in[5];
    const float* b3  = (const float*)d_in[6];
    const float* W4  = (const float*)d_in[7];
    const float* b4  = (const float*)d_in[8];
    const float* emb = (const float*)d_in[9];

    float* out     = (float*)d_out;
    float* x_recon = out;
    float* z_e     = out + (size_t)NB * DIN;
    float* z_q     = z_e + (size_t)NB * DLAT;

    float *h1, *h2, *enorm; int* idxp;
    cudaGetSymbolAddress((void**)&h1, g_h1);
    cudaGetSymbolAddress((void**)&h2, g_h2);
    cudaGetSymbolAddress((void**)&enorm, g_enorm);
    cudaGetSymbolAddress((void**)&idxp, g_idx);

    // 0) code norms
    emb_norms_kernel<<<NK/8, 256>>>(emb, enorm);

    // 1) h1 = relu(x @ W1 + b1)        [NB, DH]
    sgemm_bias_act<128,128,16,1><<<dim3(DH/128, NB/128), 256>>>(
        x, W1, b1, h1, NB, DH, DIN);

    // 2) z_e = h1 @ W2 + b2            [NB, DLAT]  -> d_out
    sgemm_bias_act<128,64,16,0><<<dim3(1, NB/128), 128>>>(
        h1, W2, b2, z_e, NB, DLAT, DH);

    // 3) idx = argmin_k ||z_e - emb_k||^2
    argmin_kernel<<<NB/128, 256>>>(z_e, emb, enorm, idxp);

    // 4) z_q = emb[idx]                [NB, DLAT]  -> d_out
    gather_zq_kernel<<<(NB*64)/256, 256>>>(idxp, emb, z_q);

    // 5) h2 = relu(z_q @ W3 + b3)      [NB, DH]
    sgemm_bias_act<128,128,16,1><<<dim3(DH/128, NB/128), 256>>>(
        z_q, W3, b3, h2, NB, DH, DLAT);

    // 6) x_recon = sigmoid(h2 @ W4 + b4)  [NB, DIN] -> d_out
    sgemm_bias_act<128,128,16,2><<<dim3((DIN + 127)/128, NB/128), 256>>>(
        h2, W4, b4, x_recon, NB, DIN, DH);
}